// round 11
// baseline (speedup 1.0000x reference)
#include <cuda_runtime.h>
#include <cuda_bf16.h>
#include <stdint.h>
#include <stddef.h>
#include <math.h>

#define Bsz 32
#define Ssz 512
#define Hsz 1024
#define Osz 1024
#define GRID 148

// ---------------- device scratch ----------------
__device__ float g_xp0[(size_t)Ssz * Bsz * 3 * Hsz];   // layer0 x-projections (s,b,3H)
__device__ float g_h1all[(size_t)Ssz * Bsz * Hsz];     // all layer1 hidden states (s,b,H)
__device__ float g_h0[Bsz * Hsz];
__device__ float g_h1[Bsz * Hsz];
__device__ float g_z0[Bsz * Hsz];
__device__ float g_z1[Bsz * Hsz];
__device__ float g_gc1[Bsz * Hsz];
__device__ float g_pz1[Bsz * Hsz];
__device__ float g_pr1[Bsz * Hsz];
// split-bf16 activations
__device__ __align__(16) __nv_bfloat16 g_h0h[Bsz * Hsz], g_h0l[Bsz * Hsz];
__device__ __align__(16) __nv_bfloat16 g_h1h[Bsz * Hsz], g_h1l[Bsz * Hsz];
__device__ __align__(16) __nv_bfloat16 g_rh0h[Bsz * Hsz], g_rh0l[Bsz * Hsz];
__device__ __align__(16) __nv_bfloat16 g_rh1h[Bsz * Hsz], g_rh1l[Bsz * Hsz];
// split-bf16 weights (recurrent path): Wh all 6 mats, Wx layer1 3 mats
__device__ __align__(16) __nv_bfloat16 g_whh[6 * 1048576], g_whl[6 * 1048576];
__device__ __align__(16) __nv_bfloat16 g_wxh[3 * 1048576], g_wxl[3 * 1048576];
__device__ unsigned g_barcnt;

__device__ __forceinline__ float sigf(float x) { return 1.f / (1.f + expf(-x)); }

__device__ __forceinline__ void split_bf16(float x, __nv_bfloat16* ph, __nv_bfloat16* pl) {
    __nv_bfloat16 h = __float2bfloat16(x);
    *ph = h;
    *pl = __float2bfloat16(x - __bfloat162float(h));
}

#define FMA16() do { \
    acc[0][0] += a.x*b.x; acc[0][1] += a.x*b.y; acc[0][2] += a.x*b.z; acc[0][3] += a.x*b.w; \
    acc[1][0] += a.y*b.x; acc[1][1] += a.y*b.y; acc[1][2] += a.y*b.z; acc[1][3] += a.y*b.w; \
    acc[2][0] += a.z*b.x; acc[2][1] += a.z*b.y; acc[2][2] += a.z*b.z; acc[2][3] += a.z*b.w; \
    acc[3][0] += a.w*b.x; acc[3][1] += a.w*b.y; acc[3][2] += a.w*b.z; acc[3][3] += a.w*b.w; \
} while (0)

// ---------------- grid barrier (monotonic counter) ----------------
__device__ __forceinline__ void gridbar(unsigned gen) {
    __syncthreads();
    __threadfence();
    if (threadIdx.x == 0) {
        atomicAdd(&g_barcnt, 1u);
        const unsigned tgt = gen * GRID;
        while (*(volatile unsigned*)&g_barcnt < tgt) { }
    }
    __syncthreads();
    __threadfence();
}

// ---------------- MMA primitives ----------------
__device__ __forceinline__ uint32_t smaddr(const void* p) {
    return (uint32_t)__cvta_generic_to_shared(p);
}
__device__ __forceinline__ void ldsm4(uint32_t addr, uint32_t& r0, uint32_t& r1,
                                      uint32_t& r2, uint32_t& r3) {
    asm volatile("ldmatrix.sync.aligned.m8n8.x4.shared.b16 {%0,%1,%2,%3}, [%4];"
                 : "=r"(r0), "=r"(r1), "=r"(r2), "=r"(r3) : "r"(addr));
}
__device__ __forceinline__ void mma16816(float* c, uint32_t a0, uint32_t a1, uint32_t a2,
                                         uint32_t a3, uint32_t b0, uint32_t b1) {
    asm volatile("mma.sync.aligned.m16n8k16.row.col.f32.bf16.bf16.f32 "
                 "{%0,%1,%2,%3}, {%4,%5,%6,%7}, {%8,%9}, {%0,%1,%2,%3};"
                 : "+f"(c[0]), "+f"(c[1]), "+f"(c[2]), "+f"(c[3])
                 : "r"(a0), "r"(a1), "r"(a2), "r"(a3), "r"(b0), "r"(b1));
}

// ---------------- init ----------------
__global__ void k_init(const float* __restrict__ h0in) {
    if (blockIdx.x == 0 && threadIdx.x == 0) g_barcnt = 0u;
    int idx = blockIdx.x * blockDim.x + threadIdx.x;
    int b = idx >> 11;
    int r = idx & 2047;
    int l = r >> 10;
    int i = r & 1023;
    float v = h0in[idx];
    int off = b * Hsz + i;
    if (l == 0) { g_h0[off] = v; split_bf16(v, &g_h0h[off], &g_h0l[off]); }
    else        { g_h1[off] = v; split_bf16(v, &g_h1h[off], &g_h1l[off]); }
}

// ---------------- weight conversion (9M elems, once per launch) ----------------
__global__ void k_wconv(const float* __restrict__ Wh, const float* __restrict__ Wx) {
    size_t idx = (size_t)blockIdx.x * 1024 + threadIdx.x;   // < 9437184
    if (idx < 6291456) {
        float v = Wh[idx];
        split_bf16(v, &g_whh[idx], &g_whl[idx]);
    } else {
        size_t o = idx - 6291456;
        float v = Wx[3145728 + o];   // Wx[1][*]
        split_bf16(v, &g_wxh[o], &g_wxl[o]);
    }
}

// ---------------- big GEMM: xp0 = x @ Wx[0]^T + bx[0] (fp32, double-buffered) ----------------
__global__ __launch_bounds__(256) void k_xproj(const float* __restrict__ x,
                                               const float* __restrict__ Wx,
                                               const float* __restrict__ bxp) {
    __shared__ __align__(16) float stage[4096];
    const int tid = threadIdx.x;
    const int bm = blockIdx.y << 6;
    const int bn = blockIdx.x << 6;
    const int lr = tid >> 2;
    const int lk = (tid & 3) << 2;
    const int mrow = bm + lr;
    const size_t a_off = ((size_t)(mrow & 31) * Ssz + (mrow >> 5)) * Hsz;
    const size_t b_off = (size_t)(bn + lr) * Hsz;
    const int tm = (tid >> 4) << 2;
    const int tn = (tid & 15) << 2;
    float acc[4][4] = {};
    float4 av = *(const float4*)(x + a_off + lk);
    float4 bv = __ldcg((const float4*)(Wx + b_off + lk));
    for (int k0 = 0; k0 < Hsz; k0 += 16) {
        float* As = stage + (((k0 >> 4) & 1) << 11);
        float* Bs = As + 1024;
        As[(lk + 0) * 64 + lr] = av.x; As[(lk + 1) * 64 + lr] = av.y;
        As[(lk + 2) * 64 + lr] = av.z; As[(lk + 3) * 64 + lr] = av.w;
        Bs[(lk + 0) * 64 + lr] = bv.x; Bs[(lk + 1) * 64 + lr] = bv.y;
        Bs[(lk + 2) * 64 + lr] = bv.z; Bs[(lk + 3) * 64 + lr] = bv.w;
        __syncthreads();
        if (k0 + 16 < Hsz) {
            av = *(const float4*)(x + a_off + k0 + 16 + lk);
            bv = __ldcg((const float4*)(Wx + b_off + k0 + 16 + lk));
        }
#pragma unroll
        for (int kk = 0; kk < 16; kk++) {
            float4 a = *(const float4*)(As + kk * 64 + tm);
            float4 b = *(const float4*)(Bs + kk * 64 + tn);
            FMA16();
        }
    }
#pragma unroll
    for (int i = 0; i < 4; i++) {
        size_t ro = (size_t)(bm + tm + i) * 3072;
#pragma unroll
        for (int j = 0; j < 4; j++) {
            int n = bn + tn + j;
            g_xp0[ro + n] = acc[i][j] + bxp[n];
        }
    }
}

// ---------------- big GEMM: out = h1all @ Wo^T + bo (fp32, double-buffered) ----------------
__global__ __launch_bounds__(256) void k_out(const float* __restrict__ Wo,
                                             const float* __restrict__ bo,
                                             float* __restrict__ out) {
    __shared__ __align__(16) float stage[4096];
    const int tid = threadIdx.x;
    const int bm = blockIdx.y << 6;
    const int bn = blockIdx.x << 6;
    const int lr = tid >> 2;
    const int lk = (tid & 3) << 2;
    const size_t a_off = (size_t)(bm + lr) * Hsz;
    const size_t b_off = (size_t)(bn + lr) * Hsz;
    const int tm = (tid >> 4) << 2;
    const int tn = (tid & 15) << 2;
    float acc[4][4] = {};
    float4 av = *(const float4*)(g_h1all + a_off + lk);
    float4 bv = __ldcg((const float4*)(Wo + b_off + lk));
    for (int k0 = 0; k0 < Hsz; k0 += 16) {
        float* As = stage + (((k0 >> 4) & 1) << 11);
        float* Bs = As + 1024;
        As[(lk + 0) * 64 + lr] = av.x; As[(lk + 1) * 64 + lr] = av.y;
        As[(lk + 2) * 64 + lr] = av.z; As[(lk + 3) * 64 + lr] = av.w;
        Bs[(lk + 0) * 64 + lr] = bv.x; Bs[(lk + 1) * 64 + lr] = bv.y;
        Bs[(lk + 2) * 64 + lr] = bv.z; Bs[(lk + 3) * 64 + lr] = bv.w;
        __syncthreads();
        if (k0 + 16 < Hsz) {
            av = *(const float4*)(g_h1all + a_off + k0 + 16 + lk);
            bv = __ldcg((const float4*)(Wo + b_off + k0 + 16 + lk));
        }
#pragma unroll
        for (int kk = 0; kk < 16; kk++) {
            float4 a = *(const float4*)(As + kk * 64 + tm);
            float4 b = *(const float4*)(Bs + kk * 64 + tn);
            FMA16();
        }
    }
#pragma unroll
    for (int i = 0; i < 4; i++) {
        int m = bm + tm + i;
        int bb = m & 31;
        int s = m >> 5;
        size_t ro = ((size_t)bb * Ssz + s) * Osz;
#pragma unroll
        for (int j = 0; j < 4; j++) {
            int n = bn + tn + j;
            out[ro + n] = acc[i][j] + bo[n];
        }
    }
}

// ---------------- split-bf16 MMA tile: C(32x64) = A(32x1024) @ W(n0..n0+63, :)^T ----
// 8 warps: warp tile m16 x n16, full K. cacc[2][4] = two n8 fragments.
__device__ __forceinline__ void mma_tile(
    const __nv_bfloat16* __restrict__ Ah, const __nv_bfloat16* __restrict__ Al,
    const __nv_bfloat16* __restrict__ Wbh, const __nv_bfloat16* __restrict__ Wbl,
    int n0, int tid, float cacc[2][4],
    __nv_bfloat16* sAh, __nv_bfloat16* sAl, __nv_bfloat16* sBh, __nv_bfloat16* sBl)
{
    const int lane = tid & 31;
    const int warp = tid >> 5;
    const int m0 = (warp & 1) << 4;
    const int nw = (warp >> 1) << 4;
    const int arow = tid >> 3;            // 0..31
    const int aoct = (tid & 7) << 3;      // 0,8,..56 (bf16 elems)

    const uint32_t adAh = smaddr(sAh + (m0 + (lane & 15)) * 72 + ((lane >> 4) << 3));
    const uint32_t adAl = smaddr(sAl + (m0 + (lane & 15)) * 72 + ((lane >> 4) << 3));
    const uint32_t adBh = smaddr(sBh + (nw + (lane & 15)) * 72 + ((lane >> 4) << 3));
    const uint32_t adBl = smaddr(sBl + (nw + (lane & 15)) * 72 + ((lane >> 4) << 3));

    uint4 vah, vall, vbh0, vbh1, vbl0, vbl1;
    vah  = *(const uint4*)(Ah + arow * Hsz + aoct);
    vall = *(const uint4*)(Al + arow * Hsz + aoct);
    vbh0 = *(const uint4*)(Wbh + (size_t)(n0 + arow) * Hsz + aoct);
    vbh1 = *(const uint4*)(Wbh + (size_t)(n0 + arow + 32) * Hsz + aoct);
    vbl0 = *(const uint4*)(Wbl + (size_t)(n0 + arow) * Hsz + aoct);
    vbl1 = *(const uint4*)(Wbl + (size_t)(n0 + arow + 32) * Hsz + aoct);

    for (int kc = 0; kc < Hsz; kc += 64) {
        __syncthreads();   // previous chunk's ldmatrix reads complete
        *(uint4*)(sAh + arow * 72 + aoct) = vah;
        *(uint4*)(sAl + arow * 72 + aoct) = vall;
        *(uint4*)(sBh + arow * 72 + aoct) = vbh0;
        *(uint4*)(sBh + (arow + 32) * 72 + aoct) = vbh1;
        *(uint4*)(sBl + arow * 72 + aoct) = vbl0;
        *(uint4*)(sBl + (arow + 32) * 72 + aoct) = vbl1;
        __syncthreads();
        if (kc + 64 < Hsz) {
            const int kn = kc + 64;
            vah  = *(const uint4*)(Ah + arow * Hsz + kn + aoct);
            vall = *(const uint4*)(Al + arow * Hsz + kn + aoct);
            vbh0 = *(const uint4*)(Wbh + (size_t)(n0 + arow) * Hsz + kn + aoct);
            vbh1 = *(const uint4*)(Wbh + (size_t)(n0 + arow + 32) * Hsz + kn + aoct);
            vbl0 = *(const uint4*)(Wbl + (size_t)(n0 + arow) * Hsz + kn + aoct);
            vbl1 = *(const uint4*)(Wbl + (size_t)(n0 + arow + 32) * Hsz + kn + aoct);
        }
#pragma unroll
        for (int ks = 0; ks < 4; ks++) {
            const uint32_t ko = ks << 5;   // 16 bf16 = 32 bytes per k-step
            uint32_t ah0, ah1, ah2, ah3, al0, al1, al2, al3;
            uint32_t bh0, bh1, bh2, bh3, bl0, bl1, bl2, bl3;
            ldsm4(adAh + ko, ah0, ah1, ah2, ah3);
            ldsm4(adAl + ko, al0, al1, al2, al3);
            ldsm4(adBh + ko, bh0, bh1, bh2, bh3);
            ldsm4(adBl + ko, bl0, bl1, bl2, bl3);
            // n8 tile 0: b0=mat0, b1=mat2 ; n8 tile 1: b0=mat1, b1=mat3
            mma16816(cacc[0], ah0, ah1, ah2, ah3, bh0, bh2);
            mma16816(cacc[0], ah0, ah1, ah2, ah3, bl0, bl2);
            mma16816(cacc[0], al0, al1, al2, al3, bh0, bh2);
            mma16816(cacc[1], ah0, ah1, ah2, ah3, bh1, bh3);
            mma16816(cacc[1], ah0, ah1, ah2, ah3, bl1, bl3);
            mma16816(cacc[1], al0, al1, al2, al3, bh1, bh3);
        }
    }
}

__device__ __forceinline__ void store_C(float cacc[2][4], int tid, float* sC) {
    const int lane = tid & 31;
    const int warp = tid >> 5;
    const int m0 = (warp & 1) << 4;
    const int nw = (warp >> 1) << 4;
    const int mr = m0 + (lane >> 2);
    const int ncb = nw + ((lane & 3) << 1);
#pragma unroll
    for (int j = 0; j < 2; j++) {
        int nc = ncb + j * 8;
        sC[mr * 64 + nc]           = cacc[j][0];
        sC[mr * 64 + nc + 1]       = cacc[j][1];
        sC[(mr + 8) * 64 + nc]     = cacc[j][2];
        sC[(mr + 8) * 64 + nc + 1] = cacc[j][3];
    }
}

// ---------------- persistent recurrence kernel (tensor-core) ----------------
__global__ __launch_bounds__(256, 1) void k_recur(const float* __restrict__ bxp) {
    __shared__ __align__(16) __nv_bfloat16 sAh[32 * 72], sAl[32 * 72];
    __shared__ __align__(16) __nv_bfloat16 sBh[64 * 72], sBl[64 * 72];
    __shared__ __align__(16) float sC[2048];
    const int tid = threadIdx.x;
    const int b = blockIdx.x;
    unsigned bar = 0;

    for (int t = 0; t < Ssz; t++) {
        const float* xp = g_xp0 + (size_t)t * Bsz * 3072;

        // ---- Phase A (64 blocks): z0, r0 (from h0) | pz1, pr1 (from h1) ----
        if (b < 64) {
            const int sel = b >> 4;
            const int n0 = (b & 15) << 6;
            const __nv_bfloat16* Asrc_h = (sel < 2) ? g_h0h : g_h1h;
            const __nv_bfloat16* Asrc_l = (sel < 2) ? g_h0l : g_h1l;
            const int widx = (sel == 0) ? 0 : (sel == 1) ? 1 : (sel == 2) ? 3 : 4;
            float cacc[2][4] = {};
            mma_tile(Asrc_h, Asrc_l, g_whh + (size_t)widx * 1048576,
                     g_whl + (size_t)widx * 1048576, n0, tid, cacc, sAh, sAl, sBh, sBl);
            __syncthreads();
            store_C(cacc, tid, sC);
            __syncthreads();
#pragma unroll
            for (int jj = 0; jj < 8; jj++) {
                int e = tid + (jj << 8);
                int m = e >> 6, n = e & 63;
                float v = sC[e];
                int i = n0 + n;
                int off = (m << 10) + i;
                if (sel == 0)      g_z0[off] = sigf(v + xp[m * 3072 + i]);
                else if (sel == 1) {
                    float r = sigf(v + xp[m * 3072 + 1024 + i]);
                    split_bf16(r * g_h0[off], &g_rh0h[off], &g_rh0l[off]);
                }
                else if (sel == 2) g_pz1[off] = v;
                else               g_pr1[off] = v;
            }
        }
        gridbar(++bar);

        // ---- Phase B (16 blocks): L0 candidate + fused h0 update ----
        if (b < 16) {
            const int n0 = b << 6;
            float cacc[2][4] = {};
            mma_tile(g_rh0h, g_rh0l, g_whh + (size_t)2 * 1048576,
                     g_whl + (size_t)2 * 1048576, n0, tid, cacc, sAh, sAl, sBh, sBl);
            __syncthreads();
            store_C(cacc, tid, sC);
            __syncthreads();
#pragma unroll
            for (int jj = 0; jj < 8; jj++) {
                int e = tid + (jj << 8);
                int m = e >> 6, n = e & 63;
                float v = sC[e];
                int i = n0 + n;
                int off = (m << 10) + i;
                float c = tanhf(v + xp[m * 3072 + 2048 + i]);
                float z = g_z0[off];
                float h = g_h0[off];
                float hn = z * h + (1.f - z) * c;
                g_h0[off] = hn;
                split_bf16(hn, &g_h0h[off], &g_h0l[off]);
            }
        }
        gridbar(++bar);

        // ---- Phase C (48 blocks): L1 x-projections + gate fuse ----
        if (b < 48) {
            const int gate = b >> 4;
            const int n0 = (b & 15) << 6;
            float cacc[2][4] = {};
            mma_tile(g_h0h, g_h0l, g_wxh + (size_t)gate * 1048576,
                     g_wxl + (size_t)gate * 1048576, n0, tid, cacc, sAh, sAl, sBh, sBl);
            __syncthreads();
            store_C(cacc, tid, sC);
            __syncthreads();
#pragma unroll
            for (int jj = 0; jj < 8; jj++) {
                int e = tid + (jj << 8);
                int m = e >> 6, n = e & 63;
                float v = sC[e];
                int i = n0 + n;
                int off = (m << 10) + i;
                float val = v + bxp[3072 + (gate << 10) + i];
                if (gate == 0)      g_z1[off] = sigf(val + g_pz1[off]);
                else if (gate == 1) {
                    float r = sigf(val + g_pr1[off]);
                    split_bf16(r * g_h1[off], &g_rh1h[off], &g_rh1l[off]);
                }
                else                g_gc1[off] = val;
            }
        }
        gridbar(++bar);

        // ---- Phase D (16 blocks): L1 candidate + fused h1 update + store ----
        if (b < 16) {
            const int n0 = b << 6;
            float cacc[2][4] = {};
            mma_tile(g_rh1h, g_rh1l, g_whh + (size_t)5 * 1048576,
                     g_whl + (size_t)5 * 1048576, n0, tid, cacc, sAh, sAl, sBh, sBl);
            __syncthreads();
            store_C(cacc, tid, sC);
            __syncthreads();
#pragma unroll
            for (int jj = 0; jj < 8; jj++) {
                int e = tid + (jj << 8);
                int m = e >> 6, n = e & 63;
                float v = sC[e];
                int i = n0 + n;
                int off = (m << 10) + i;
                float c = tanhf(v + g_gc1[off]);
                float z = g_z1[off];
                float h = g_h1[off];
                float hn = z * h + (1.f - z) * c;
                g_h1[off] = hn;
                split_bf16(hn, &g_h1h[off], &g_h1l[off]);
                g_h1all[(size_t)t * Bsz * Hsz + off] = hn;
            }
        }
        gridbar(++bar);
    }
}

// ---- final hidden state (B,L,H) appended after layer_output ----
__global__ void k_hid(float* __restrict__ out) {
    int idx = blockIdx.x * blockDim.x + threadIdx.x;
    int b = idx >> 11;
    int r = idx & 2047;
    int l = r >> 10;
    int i = r & 1023;
    out[(size_t)Bsz * Ssz * Osz + idx] = (l == 0 ? g_h0 : g_h1)[b * Hsz + i];
}

// ---------------- launch (6 graph nodes) ----------------
extern "C" void kernel_launch(void* const* d_in, const int* in_sizes, int n_in,
                              void* d_out, int out_size) {
    const float* x   = (const float*)d_in[0];
    const float* h0  = (const float*)d_in[1];
    const float* Wx  = (const float*)d_in[2];
    const float* Wh  = (const float*)d_in[3];
    const float* bx  = (const float*)d_in[4];
    const float* Wo  = (const float*)d_in[5];
    const float* bo  = (const float*)d_in[6];
    float* out = (float*)d_out;

    k_init<<<64, 1024>>>(h0);
    k_wconv<<<9216, 1024>>>(Wh, Wx);
    k_xproj<<<dim3(48, 256), 256>>>(x, Wx, bx);
    k_recur<<<GRID, 256>>>(bx);
    k_out<<<dim3(16, 256), 256>>>(Wo, bo, out);
    k_hid<<<64, 1024>>>(out);
}

// round 12
// speedup vs baseline: 1.2149x; 1.2149x over previous
#include <cuda_runtime.h>
#include <cuda_bf16.h>
#include <stdint.h>
#include <stddef.h>
#include <math.h>

#define Bsz 32
#define Ssz 512
#define Hsz 1024
#define Osz 1024
#define GRID 148

// stage layout (bf16 elems): A_h[32*72] | A_l[32*72] | B_h[64*72] | B_l[64*72]
#define STG_ELEMS 13824          // 192*72
#define SMEM_BYTES (4 * STG_ELEMS * 2)   // 110592

// ---------------- device scratch ----------------
__device__ float g_xp0[(size_t)Ssz * Bsz * 3 * Hsz];
__device__ float g_h1all[(size_t)Ssz * Bsz * Hsz];
__device__ float g_h0[Bsz * Hsz];
__device__ float g_h1[Bsz * Hsz];
__device__ float g_z0[Bsz * Hsz];
__device__ float g_z1[Bsz * Hsz];
__device__ float g_gc1[Bsz * Hsz];
__device__ float g_pz1[Bsz * Hsz];
__device__ float g_pr1[Bsz * Hsz];
// split-bf16 activations
__device__ __align__(16) __nv_bfloat16 g_h0h[Bsz * Hsz], g_h0l[Bsz * Hsz];
__device__ __align__(16) __nv_bfloat16 g_h1h[Bsz * Hsz], g_h1l[Bsz * Hsz];
__device__ __align__(16) __nv_bfloat16 g_rh0h[Bsz * Hsz], g_rh0l[Bsz * Hsz];
__device__ __align__(16) __nv_bfloat16 g_rh1h[Bsz * Hsz], g_rh1l[Bsz * Hsz];
// split-bf16 weights
__device__ __align__(16) __nv_bfloat16 g_whh[6 * 1048576], g_whl[6 * 1048576];
__device__ __align__(16) __nv_bfloat16 g_wxh[3 * 1048576], g_wxl[3 * 1048576];
// K-split partials + tickets
__device__ float g_partA[8 * 32768];   // [slice(2)][sel(4)][32][1024]
__device__ float g_partB[4 * 32768];
__device__ float g_partC[6 * 32768];   // [slice(2)][gate(3)][32][1024]
__device__ float g_partD[4 * 32768];
__device__ unsigned g_tickA[64], g_tickB[16], g_tickC[48], g_tickD[16];
__device__ unsigned g_barcnt;

__device__ __forceinline__ float sigf(float x) { return 1.f / (1.f + expf(-x)); }

__device__ __forceinline__ void split_bf16(float x, __nv_bfloat16* ph, __nv_bfloat16* pl) {
    __nv_bfloat16 h = __float2bfloat16(x);
    *ph = h;
    *pl = __float2bfloat16(x - __bfloat162float(h));
}

#define FMA16() do { \
    acc[0][0] += a.x*b.x; acc[0][1] += a.x*b.y; acc[0][2] += a.x*b.z; acc[0][3] += a.x*b.w; \
    acc[1][0] += a.y*b.x; acc[1][1] += a.y*b.y; acc[1][2] += a.y*b.z; acc[1][3] += a.y*b.w; \
    acc[2][0] += a.z*b.x; acc[2][1] += a.z*b.y; acc[2][2] += a.z*b.z; acc[2][3] += a.z*b.w; \
    acc[3][0] += a.w*b.x; acc[3][1] += a.w*b.y; acc[3][2] += a.w*b.z; acc[3][3] += a.w*b.w; \
} while (0)

// ---------------- grid barrier ----------------
__device__ __forceinline__ void gridbar(unsigned gen) {
    __syncthreads();
    __threadfence();
    if (threadIdx.x == 0) {
        atomicAdd(&g_barcnt, 1u);
        const unsigned tgt = gen * GRID;
        while (*(volatile unsigned*)&g_barcnt < tgt) { }
    }
    __syncthreads();
    __threadfence();
}

// ---------------- MMA / async primitives ----------------
__device__ __forceinline__ uint32_t smaddr(const void* p) {
    return (uint32_t)__cvta_generic_to_shared(p);
}
__device__ __forceinline__ void cpa16(uint32_t dst, const void* src) {
    asm volatile("cp.async.cg.shared.global [%0], [%1], 16;" :: "r"(dst), "l"(src));
}
__device__ __forceinline__ void ldsm4(uint32_t addr, uint32_t& r0, uint32_t& r1,
                                      uint32_t& r2, uint32_t& r3) {
    asm volatile("ldmatrix.sync.aligned.m8n8.x4.shared.b16 {%0,%1,%2,%3}, [%4];"
                 : "=r"(r0), "=r"(r1), "=r"(r2), "=r"(r3) : "r"(addr));
}
__device__ __forceinline__ void mma16816(float* c, uint32_t a0, uint32_t a1, uint32_t a2,
                                         uint32_t a3, uint32_t b0, uint32_t b1) {
    asm volatile("mma.sync.aligned.m16n8k16.row.col.f32.bf16.bf16.f32 "
                 "{%0,%1,%2,%3}, {%4,%5,%6,%7}, {%8,%9}, {%0,%1,%2,%3};"
                 : "+f"(c[0]), "+f"(c[1]), "+f"(c[2]), "+f"(c[3])
                 : "r"(a0), "r"(a1), "r"(a2), "r"(a3), "r"(b0), "r"(b1));
}

// ---------------- init ----------------
__global__ void k_init(const float* __restrict__ h0in) {
    if (blockIdx.x == 0 && threadIdx.x == 0) g_barcnt = 0u;
    int idx = blockIdx.x * blockDim.x + threadIdx.x;
    int b = idx >> 11;
    int r = idx & 2047;
    int l = r >> 10;
    int i = r & 1023;
    float v = h0in[idx];
    int off = b * Hsz + i;
    if (l == 0) { g_h0[off] = v; split_bf16(v, &g_h0h[off], &g_h0l[off]); }
    else        { g_h1[off] = v; split_bf16(v, &g_h1h[off], &g_h1l[off]); }
}

// ---------------- weight conversion ----------------
__global__ void k_wconv(const float* __restrict__ Wh, const float* __restrict__ Wx) {
    size_t idx = (size_t)blockIdx.x * 1024 + threadIdx.x;
    if (idx < 6291456) {
        float v = Wh[idx];
        split_bf16(v, &g_whh[idx], &g_whl[idx]);
    } else {
        size_t o = idx - 6291456;
        float v = Wx[3145728 + o];
        split_bf16(v, &g_wxh[o], &g_wxl[o]);
    }
}

// ---------------- big GEMM: xp0 = x @ Wx[0]^T + bx[0] (fp32) ----------------
__global__ __launch_bounds__(256) void k_xproj(const float* __restrict__ x,
                                               const float* __restrict__ Wx,
                                               const float* __restrict__ bxp) {
    __shared__ __align__(16) float stage[4096];
    const int tid = threadIdx.x;
    const int bm = blockIdx.y << 6;
    const int bn = blockIdx.x << 6;
    const int lr = tid >> 2;
    const int lk = (tid & 3) << 2;
    const int mrow = bm + lr;
    const size_t a_off = ((size_t)(mrow & 31) * Ssz + (mrow >> 5)) * Hsz;
    const size_t b_off = (size_t)(bn + lr) * Hsz;
    const int tm = (tid >> 4) << 2;
    const int tn = (tid & 15) << 2;
    float acc[4][4] = {};
    float4 av = *(const float4*)(x + a_off + lk);
    float4 bv = __ldcg((const float4*)(Wx + b_off + lk));
    for (int k0 = 0; k0 < Hsz; k0 += 16) {
        float* As = stage + (((k0 >> 4) & 1) << 11);
        float* Bs = As + 1024;
        As[(lk + 0) * 64 + lr] = av.x; As[(lk + 1) * 64 + lr] = av.y;
        As[(lk + 2) * 64 + lr] = av.z; As[(lk + 3) * 64 + lr] = av.w;
        Bs[(lk + 0) * 64 + lr] = bv.x; Bs[(lk + 1) * 64 + lr] = bv.y;
        Bs[(lk + 2) * 64 + lr] = bv.z; Bs[(lk + 3) * 64 + lr] = bv.w;
        __syncthreads();
        if (k0 + 16 < Hsz) {
            av = *(const float4*)(x + a_off + k0 + 16 + lk);
            bv = __ldcg((const float4*)(Wx + b_off + k0 + 16 + lk));
        }
#pragma unroll
        for (int kk = 0; kk < 16; kk++) {
            float4 a = *(const float4*)(As + kk * 64 + tm);
            float4 b = *(const float4*)(Bs + kk * 64 + tn);
            FMA16();
        }
    }
#pragma unroll
    for (int i = 0; i < 4; i++) {
        size_t ro = (size_t)(bm + tm + i) * 3072;
#pragma unroll
        for (int j = 0; j < 4; j++) {
            int n = bn + tn + j;
            g_xp0[ro + n] = acc[i][j] + bxp[n];
        }
    }
}

// ---------------- big GEMM: out = h1all @ Wo^T + bo (fp32) ----------------
__global__ __launch_bounds__(256) void k_out(const float* __restrict__ Wo,
                                             const float* __restrict__ bo,
                                             float* __restrict__ out) {
    __shared__ __align__(16) float stage[4096];
    const int tid = threadIdx.x;
    const int bm = blockIdx.y << 6;
    const int bn = blockIdx.x << 6;
    const int lr = tid >> 2;
    const int lk = (tid & 3) << 2;
    const size_t a_off = (size_t)(bm + lr) * Hsz;
    const size_t b_off = (size_t)(bn + lr) * Hsz;
    const int tm = (tid >> 4) << 2;
    const int tn = (tid & 15) << 2;
    float acc[4][4] = {};
    float4 av = *(const float4*)(g_h1all + a_off + lk);
    float4 bv = __ldcg((const float4*)(Wo + b_off + lk));
    for (int k0 = 0; k0 < Hsz; k0 += 16) {
        float* As = stage + (((k0 >> 4) & 1) << 11);
        float* Bs = As + 1024;
        As[(lk + 0) * 64 + lr] = av.x; As[(lk + 1) * 64 + lr] = av.y;
        As[(lk + 2) * 64 + lr] = av.z; As[(lk + 3) * 64 + lr] = av.w;
        Bs[(lk + 0) * 64 + lr] = bv.x; Bs[(lk + 1) * 64 + lr] = bv.y;
        Bs[(lk + 2) * 64 + lr] = bv.z; Bs[(lk + 3) * 64 + lr] = bv.w;
        __syncthreads();
        if (k0 + 16 < Hsz) {
            av = *(const float4*)(g_h1all + a_off + k0 + 16 + lk);
            bv = __ldcg((const float4*)(Wo + b_off + k0 + 16 + lk));
        }
#pragma unroll
        for (int kk = 0; kk < 16; kk++) {
            float4 a = *(const float4*)(As + kk * 64 + tm);
            float4 b = *(const float4*)(Bs + kk * 64 + tn);
            FMA16();
        }
    }
#pragma unroll
    for (int i = 0; i < 4; i++) {
        int m = bm + tm + i;
        int bb = m & 31;
        int s = m >> 5;
        size_t ro = ((size_t)bb * Ssz + s) * Osz;
#pragma unroll
        for (int j = 0; j < 4; j++) {
            int n = bn + tn + j;
            out[ro + n] = acc[i][j] + bo[n];
        }
    }
}

// ---------------- async chunk issue (64 k, hi+lo, A 32 rows + B 64 rows) ----------------
__device__ __forceinline__ void issue_chunk(
    const __nv_bfloat16* __restrict__ Ah, const __nv_bfloat16* __restrict__ Al,
    const __nv_bfloat16* __restrict__ Wbh, const __nv_bfloat16* __restrict__ Wbl,
    int n0, int kk, __nv_bfloat16* st, int arow, int koct)
{
    uint32_t base = smaddr(st);
    uint32_t dA = base + (uint32_t)(arow * 72 + koct) * 2;
    const size_t asrc = (size_t)arow * Hsz + kk + koct;
    cpa16(dA,        Ah + asrc);
    cpa16(dA + 4608, Al + asrc);
    const size_t b0 = (size_t)(n0 + arow) * Hsz + kk + koct;
    const size_t b1 = (size_t)(n0 + arow + 32) * Hsz + kk + koct;
    uint32_t dB = base + 9216 + (uint32_t)(arow * 72 + koct) * 2;
    cpa16(dB,               Wbh + b0);
    cpa16(dB + 4608,        Wbh + b1);
    cpa16(dB + 9216,        Wbl + b0);
    cpa16(dB + 9216 + 4608, Wbl + b1);
    asm volatile("cp.async.commit_group;" ::: "memory");
}

// ---------------- pipelined split-bf16 MMA tile: C(32x64) += A(32xklen) @ W^T ----------------
__device__ __forceinline__ void mma_tile_async(
    const __nv_bfloat16* __restrict__ Ah, const __nv_bfloat16* __restrict__ Al,
    const __nv_bfloat16* __restrict__ Wbh, const __nv_bfloat16* __restrict__ Wbl,
    int n0, int kbase, int nchunks, int tid, float cacc[2][4], __nv_bfloat16* sm)
{
    const int lane = tid & 31, warp = tid >> 5;
    const int m0 = (warp & 1) << 4, nw = (warp >> 1) << 4;
    const int arow = tid >> 3, koct = (tid & 7) << 3;
    const int aoff = (m0 + (lane & 15)) * 72 + ((lane >> 4) << 3);
    const int boff = (nw + (lane & 15)) * 72 + ((lane >> 4) << 3);

    issue_chunk(Ah, Al, Wbh, Wbl, n0, kbase,      sm,             arow, koct);
    issue_chunk(Ah, Al, Wbh, Wbl, n0, kbase + 64, sm + STG_ELEMS, arow, koct);

    for (int kc = 0; kc < nchunks; kc++) {
        if (kc + 2 < nchunks)
            issue_chunk(Ah, Al, Wbh, Wbl, n0, kbase + ((kc + 2) << 6),
                        sm + ((kc + 2) & 3) * STG_ELEMS, arow, koct);
        else
            asm volatile("cp.async.commit_group;" ::: "memory");
        asm volatile("cp.async.wait_group 2;" ::: "memory");
        __syncthreads();
        __nv_bfloat16* st = sm + (kc & 3) * STG_ELEMS;
        uint32_t adAh = smaddr(st + aoff);
        uint32_t adAl = smaddr(st + 2304 + aoff);
        uint32_t adBh = smaddr(st + 4608 + boff);
        uint32_t adBl = smaddr(st + 9216 + boff);
#pragma unroll
        for (int ks = 0; ks < 4; ks++) {
            const uint32_t ko = ks << 5;
            uint32_t ah0, ah1, ah2, ah3, al0, al1, al2, al3;
            uint32_t bh0, bh1, bh2, bh3, bl0, bl1, bl2, bl3;
            ldsm4(adAh + ko, ah0, ah1, ah2, ah3);
            ldsm4(adAl + ko, al0, al1, al2, al3);
            ldsm4(adBh + ko, bh0, bh1, bh2, bh3);
            ldsm4(adBl + ko, bl0, bl1, bl2, bl3);
            mma16816(cacc[0], ah0, ah1, ah2, ah3, bh0, bh2);
            mma16816(cacc[0], ah0, ah1, ah2, ah3, bl0, bl2);
            mma16816(cacc[0], al0, al1, al2, al3, bh0, bh2);
            mma16816(cacc[1], ah0, ah1, ah2, ah3, bh1, bh3);
            mma16816(cacc[1], ah0, ah1, ah2, ah3, bl1, bl3);
            mma16816(cacc[1], al0, al1, al2, al3, bh1, bh3);
        }
    }
}

// store fragments to a fp32 partial plane at [(m<<10) + n0 + col]
#define FRAG_STORE(dst) do { \
    _Pragma("unroll") for (int j_ = 0; j_ < 2; j_++) \
    _Pragma("unroll") for (int e_ = 0; e_ < 4; e_++) { \
        int m_ = erow + ((e_ >> 1) << 3); \
        int i_ = n0 + ecol + (j_ << 3) + (e_ & 1); \
        (dst)[(m_ << 10) + i_] = cacc[j_][e_]; \
    } } while (0)

// ---------------- persistent recurrence kernel (async tensor-core) ----------------
__global__ __launch_bounds__(256, 1) void k_recur(const float* __restrict__ bxp) {
    extern __shared__ __nv_bfloat16 smdyn[];
    __shared__ int s_win;
    const int tid = threadIdx.x;
    const int b = blockIdx.x;
    const int lane = tid & 31, warp = tid >> 5;
    const int erow = ((warp & 1) << 4) + (lane >> 2);
    const int ecol = ((warp >> 1) << 4) + ((lane & 3) << 1);
    unsigned bar = 0;

    for (int t = 0; t < Ssz; t++) {
        const float* xp = g_xp0 + (size_t)t * Bsz * 3072;

        // ---- Phase A (128 blocks): z0,r0 (h0) | pz1,pr1 (h1); K-split x2 ----
        if (b < 128) {
            const int slice = b & 1, task = b >> 1;
            const int sel = task >> 4, n0 = (task & 15) << 6;
            const __nv_bfloat16* Asrc_h = (sel < 2) ? g_h0h : g_h1h;
            const __nv_bfloat16* Asrc_l = (sel < 2) ? g_h0l : g_h1l;
            const int widx = (sel == 0) ? 0 : (sel == 1) ? 1 : (sel == 2) ? 3 : 4;
            float cacc[2][4] = {};
            mma_tile_async(Asrc_h, Asrc_l, g_whh + (size_t)widx * 1048576,
                           g_whl + (size_t)widx * 1048576, n0, slice << 9, 8,
                           tid, cacc, smdyn);
            FRAG_STORE(g_partA + (((slice << 2) + sel) << 15));
            __threadfence();
            __syncthreads();
            if (tid == 0) s_win = ((atomicAdd(&g_tickA[task], 1u) & 1u) == 1u) ? 1 : 0;
            __syncthreads();
            if (s_win) {
                const float* p0 = g_partA + (sel << 15);
                const float* p1 = g_partA + ((4 + sel) << 15);
#pragma unroll
                for (int jj = 0; jj < 8; jj++) {
                    int e = tid + (jj << 8);
                    int m = e >> 6;
                    int i = n0 + (e & 63);
                    int off = (m << 10) + i;
                    float v = __ldcg(p0 + off) + __ldcg(p1 + off);
                    if (sel == 0)      g_z0[off] = sigf(v + xp[m * 3072 + i]);
                    else if (sel == 1) {
                        float r = sigf(v + xp[m * 3072 + 1024 + i]);
                        split_bf16(r * g_h0[off], &g_rh0h[off], &g_rh0l[off]);
                    }
                    else if (sel == 2) g_pz1[off] = v;
                    else               g_pr1[off] = v;
                }
            }
        }
        gridbar(++bar);

        // ---- Phase B (64 blocks): L0 candidate; K-split x4; winner updates h0 ----
        if (b < 64) {
            const int slice = b & 3, tile = b >> 2, n0 = tile << 6;
            float cacc[2][4] = {};
            mma_tile_async(g_rh0h, g_rh0l, g_whh + (size_t)2 * 1048576,
                           g_whl + (size_t)2 * 1048576, n0, slice << 8, 4,
                           tid, cacc, smdyn);
            FRAG_STORE(g_partB + (slice << 15));
            __threadfence();
            __syncthreads();
            if (tid == 0) s_win = ((atomicAdd(&g_tickB[tile], 1u) & 3u) == 3u) ? 1 : 0;
            __syncthreads();
            if (s_win) {
#pragma unroll
                for (int jj = 0; jj < 8; jj++) {
                    int e = tid + (jj << 8);
                    int m = e >> 6;
                    int i = n0 + (e & 63);
                    int off = (m << 10) + i;
                    float v = __ldcg(g_partB + off) + __ldcg(g_partB + 32768 + off)
                            + __ldcg(g_partB + 65536 + off) + __ldcg(g_partB + 98304 + off);
                    float c = tanhf(v + xp[m * 3072 + 2048 + i]);
                    float z = g_z0[off];
                    float h = g_h0[off];
                    float hn = z * h + (1.f - z) * c;
                    g_h0[off] = hn;
                    split_bf16(hn, &g_h0h[off], &g_h0l[off]);
                }
            }
        }
        gridbar(++bar);

        // ---- Phase C (96 blocks): L1 x-projections; K-split x2 ----
        if (b < 96) {
            const int slice = b & 1, task = b >> 1;
            const int gate = task >> 4, n0 = (task & 15) << 6;
            float cacc[2][4] = {};
            mma_tile_async(g_h0h, g_h0l, g_wxh + (size_t)gate * 1048576,
                           g_wxl + (size_t)gate * 1048576, n0, slice << 9, 8,
                           tid, cacc, smdyn);
            FRAG_STORE(g_partC + ((slice * 3 + gate) << 15));
            __threadfence();
            __syncthreads();
            if (tid == 0) s_win = ((atomicAdd(&g_tickC[task], 1u) & 1u) == 1u) ? 1 : 0;
            __syncthreads();
            if (s_win) {
                const float* p0 = g_partC + (gate << 15);
                const float* p1 = g_partC + ((3 + gate) << 15);
#pragma unroll
                for (int jj = 0; jj < 8; jj++) {
                    int e = tid + (jj << 8);
                    int m = e >> 6;
                    int i = n0 + (e & 63);
                    int off = (m << 10) + i;
                    float val = __ldcg(p0 + off) + __ldcg(p1 + off)
                              + bxp[3072 + (gate << 10) + i];
                    if (gate == 0)      g_z1[off] = sigf(val + g_pz1[off]);
                    else if (gate == 1) {
                        float r = sigf(val + g_pr1[off]);
                        split_bf16(r * g_h1[off], &g_rh1h[off], &g_rh1l[off]);
                    }
                    else                g_gc1[off] = val;
                }
            }
        }
        gridbar(++bar);

        // ---- Phase D (64 blocks): L1 candidate; K-split x4; winner updates h1 ----
        if (b < 64) {
            const int slice = b & 3, tile = b >> 2, n0 = tile << 6;
            float cacc[2][4] = {};
            mma_tile_async(g_rh1h, g_rh1l, g_whh + (size_t)5 * 1048576,
                           g_whl + (size_t)5 * 1048576, n0, slice << 8, 4,
                           tid, cacc, smdyn);
            FRAG_STORE(g_partD + (slice << 15));
            __threadfence();
            __syncthreads();
            if (tid == 0) s_win = ((atomicAdd(&g_tickD[tile], 1u) & 3u) == 3u) ? 1 : 0;
            __syncthreads();
            if (s_win) {
#pragma unroll
                for (int jj = 0; jj < 8; jj++) {
                    int e = tid + (jj << 8);
                    int m = e >> 6;
                    int i = n0 + (e & 63);
                    int off = (m << 10) + i;
                    float v = __ldcg(g_partD + off) + __ldcg(g_partD + 32768 + off)
                            + __ldcg(g_partD + 65536 + off) + __ldcg(g_partD + 98304 + off);
                    float c = tanhf(v + g_gc1[off]);
                    float z = g_z1[off];
                    float h = g_h1[off];
                    float hn = z * h + (1.f - z) * c;
                    g_h1[off] = hn;
                    split_bf16(hn, &g_h1h[off], &g_h1l[off]);
                    g_h1all[(size_t)t * Bsz * Hsz + off] = hn;
                }
            }
        }
        gridbar(++bar);
    }
}

// ---- final hidden state (B,L,H) appended after layer_output ----
__global__ void k_hid(float* __restrict__ out) {
    int idx = blockIdx.x * blockDim.x + threadIdx.x;
    int b = idx >> 11;
    int r = idx & 2047;
    int l = r >> 10;
    int i = r & 1023;
    out[(size_t)Bsz * Ssz * Osz + idx] = (l == 0 ? g_h0 : g_h1)[b * Hsz + i];
}

// ---------------- launch (6 graph nodes) ----------------
extern "C" void kernel_launch(void* const* d_in, const int* in_sizes, int n_in,
                              void* d_out, int out_size) {
    const float* x   = (const float*)d_in[0];
    const float* h0  = (const float*)d_in[1];
    const float* Wx  = (const float*)d_in[2];
    const float* Wh  = (const float*)d_in[3];
    const float* bx  = (const float*)d_in[4];
    const float* Wo  = (const float*)d_in[5];
    const float* bo  = (const float*)d_in[6];
    float* out = (float*)d_out;

    cudaFuncSetAttribute(k_recur, cudaFuncAttributeMaxDynamicSharedMemorySize, SMEM_BYTES);

    k_init<<<64, 1024>>>(h0);
    k_wconv<<<9216, 1024>>>(Wh, Wx);
    k_xproj<<<dim3(48, 256), 256>>>(x, Wx, bx);
    k_recur<<<GRID, 256, SMEM_BYTES>>>(bx);
    k_out<<<dim3(16, 256), 256>>>(Wo, bo, out);
    k_hid<<<64, 1024>>>(out);
}

// round 13
// speedup vs baseline: 1.2715x; 1.0466x over previous
#include <cuda_runtime.h>
#include <cuda_bf16.h>
#include <stdint.h>
#include <stddef.h>
#include <math.h>

#define Bsz 32
#define Ssz 512
#define Hsz 1024
#define Osz 1024
#define GRID 128

// stage layout (bf16 elems): A_h[32*72] | A_l[32*72] | B_h[64*72] | B_l[64*72]
#define STG_ELEMS 13824          // 192*72
#define SMEM_BYTES (4 * STG_ELEMS * 2)   // 110592

// ---------------- device scratch ----------------
__device__ float g_xp0[(size_t)Ssz * Bsz * 3 * Hsz];
__device__ float g_h1all[(size_t)Ssz * Bsz * Hsz];
__device__ float g_h0[Bsz * Hsz];
__device__ float g_h1[Bsz * Hsz];
__device__ float g_z0[Bsz * Hsz];
__device__ float g_z1[Bsz * Hsz];
// split-bf16 activations
__device__ __align__(16) __nv_bfloat16 g_h0h[Bsz * Hsz], g_h0l[Bsz * Hsz];
__device__ __align__(16) __nv_bfloat16 g_h1h[Bsz * Hsz], g_h1l[Bsz * Hsz];
__device__ __align__(16) __nv_bfloat16 g_rh0h[Bsz * Hsz], g_rh0l[Bsz * Hsz];
__device__ __align__(16) __nv_bfloat16 g_rh1h[Bsz * Hsz], g_rh1l[Bsz * Hsz];
// split-bf16 weights
__device__ __align__(16) __nv_bfloat16 g_whh[6 * 1048576], g_whl[6 * 1048576];
__device__ __align__(16) __nv_bfloat16 g_wxh[3 * 1048576], g_wxl[3 * 1048576];
// K-split partials + tickets
__device__ float g_pA[8 * 32768];   // [slice4][gem2]
__device__ float g_pB[8 * 32768];   // [slice8]
__device__ float g_pC[8 * 32768];   // [slice4][gate2]
__device__ float g_pD[8 * 32768];   // [slice8]
__device__ unsigned g_tkA[32], g_tkB[16], g_tkC[32], g_tkD[16];
__device__ unsigned g_barcnt;

__device__ __forceinline__ float sigf(float x) { return 1.f / (1.f + expf(-x)); }

__device__ __forceinline__ void split_bf16(float x, __nv_bfloat16* ph, __nv_bfloat16* pl) {
    __nv_bfloat16 h = __float2bfloat16(x);
    *ph = h;
    *pl = __float2bfloat16(x - __bfloat162float(h));
}

#define FMA16() do { \
    acc[0][0] += a.x*b.x; acc[0][1] += a.x*b.y; acc[0][2] += a.x*b.z; acc[0][3] += a.x*b.w; \
    acc[1][0] += a.y*b.x; acc[1][1] += a.y*b.y; acc[1][2] += a.y*b.z; acc[1][3] += a.y*b.w; \
    acc[2][0] += a.z*b.x; acc[2][1] += a.z*b.y; acc[2][2] += a.z*b.z; acc[2][3] += a.z*b.w; \
    acc[3][0] += a.w*b.x; acc[3][1] += a.w*b.y; acc[3][2] += a.w*b.z; acc[3][3] += a.w*b.w; \
} while (0)

// ---------------- grid barrier ----------------
__device__ __forceinline__ void gridbar(unsigned gen) {
    __syncthreads();
    __threadfence();
    if (threadIdx.x == 0) {
        atomicAdd(&g_barcnt, 1u);
        const unsigned tgt = gen * GRID;
        while (*(volatile unsigned*)&g_barcnt < tgt) { }
    }
    __syncthreads();
    __threadfence();
}

// ---------------- MMA / async primitives ----------------
__device__ __forceinline__ uint32_t smaddr(const void* p) {
    return (uint32_t)__cvta_generic_to_shared(p);
}
__device__ __forceinline__ void cpa16(uint32_t dst, const void* src) {
    asm volatile("cp.async.cg.shared.global [%0], [%1], 16;" :: "r"(dst), "l"(src));
}
__device__ __forceinline__ void ldsm4(uint32_t addr, uint32_t& r0, uint32_t& r1,
                                      uint32_t& r2, uint32_t& r3) {
    asm volatile("ldmatrix.sync.aligned.m8n8.x4.shared.b16 {%0,%1,%2,%3}, [%4];"
                 : "=r"(r0), "=r"(r1), "=r"(r2), "=r"(r3) : "r"(addr));
}
__device__ __forceinline__ void mma16816(float* c, uint32_t a0, uint32_t a1, uint32_t a2,
                                         uint32_t a3, uint32_t b0, uint32_t b1) {
    asm volatile("mma.sync.aligned.m16n8k16.row.col.f32.bf16.bf16.f32 "
                 "{%0,%1,%2,%3}, {%4,%5,%6,%7}, {%8,%9}, {%0,%1,%2,%3};"
                 : "+f"(c[0]), "+f"(c[1]), "+f"(c[2]), "+f"(c[3])
                 : "r"(a0), "r"(a1), "r"(a2), "r"(a3), "r"(b0), "r"(b1));
}

// ---------------- init ----------------
__global__ void k_init(const float* __restrict__ h0in) {
    if (blockIdx.x == 0 && threadIdx.x == 0) g_barcnt = 0u;
    int idx = blockIdx.x * blockDim.x + threadIdx.x;
    int b = idx >> 11;
    int r = idx & 2047;
    int l = r >> 10;
    int i = r & 1023;
    float v = h0in[idx];
    int off = b * Hsz + i;
    if (l == 0) { g_h0[off] = v; split_bf16(v, &g_h0h[off], &g_h0l[off]); }
    else        { g_h1[off] = v; split_bf16(v, &g_h1h[off], &g_h1l[off]); }
}

// ---------------- weight conversion ----------------
__global__ void k_wconv(const float* __restrict__ Wh, const float* __restrict__ Wx) {
    size_t idx = (size_t)blockIdx.x * 1024 + threadIdx.x;
    if (idx < 6291456) {
        float v = Wh[idx];
        split_bf16(v, &g_whh[idx], &g_whl[idx]);
    } else {
        size_t o = idx - 6291456;
        float v = Wx[3145728 + o];
        split_bf16(v, &g_wxh[o], &g_wxl[o]);
    }
}

// ---------------- big GEMM: xp0 = x @ Wx[0]^T + bx[0] (fp32) ----------------
__global__ __launch_bounds__(256) void k_xproj(const float* __restrict__ x,
                                               const float* __restrict__ Wx,
                                               const float* __restrict__ bxp) {
    __shared__ __align__(16) float stage[4096];
    const int tid = threadIdx.x;
    const int bm = blockIdx.y << 6;
    const int bn = blockIdx.x << 6;
    const int lr = tid >> 2;
    const int lk = (tid & 3) << 2;
    const int mrow = bm + lr;
    const size_t a_off = ((size_t)(mrow & 31) * Ssz + (mrow >> 5)) * Hsz;
    const size_t b_off = (size_t)(bn + lr) * Hsz;
    const int tm = (tid >> 4) << 2;
    const int tn = (tid & 15) << 2;
    float acc[4][4] = {};
    float4 av = *(const float4*)(x + a_off + lk);
    float4 bv = __ldcg((const float4*)(Wx + b_off + lk));
    for (int k0 = 0; k0 < Hsz; k0 += 16) {
        float* As = stage + (((k0 >> 4) & 1) << 11);
        float* Bs = As + 1024;
        As[(lk + 0) * 64 + lr] = av.x; As[(lk + 1) * 64 + lr] = av.y;
        As[(lk + 2) * 64 + lr] = av.z; As[(lk + 3) * 64 + lr] = av.w;
        Bs[(lk + 0) * 64 + lr] = bv.x; Bs[(lk + 1) * 64 + lr] = bv.y;
        Bs[(lk + 2) * 64 + lr] = bv.z; Bs[(lk + 3) * 64 + lr] = bv.w;
        __syncthreads();
        if (k0 + 16 < Hsz) {
            av = *(const float4*)(x + a_off + k0 + 16 + lk);
            bv = __ldcg((const float4*)(Wx + b_off + k0 + 16 + lk));
        }
#pragma unroll
        for (int kk = 0; kk < 16; kk++) {
            float4 a = *(const float4*)(As + kk * 64 + tm);
            float4 b = *(const float4*)(Bs + kk * 64 + tn);
            FMA16();
        }
    }
#pragma unroll
    for (int i = 0; i < 4; i++) {
        size_t ro = (size_t)(bm + tm + i) * 3072;
#pragma unroll
        for (int j = 0; j < 4; j++) {
            int n = bn + tn + j;
            g_xp0[ro + n] = acc[i][j] + bxp[n];
        }
    }
}

// ---------------- big GEMM: out = h1all @ Wo^T + bo (fp32) ----------------
__global__ __launch_bounds__(256) void k_out(const float* __restrict__ Wo,
                                             const float* __restrict__ bo,
                                             float* __restrict__ out) {
    __shared__ __align__(16) float stage[4096];
    const int tid = threadIdx.x;
    const int bm = blockIdx.y << 6;
    const int bn = blockIdx.x << 6;
    const int lr = tid >> 2;
    const int lk = (tid & 3) << 2;
    const size_t a_off = (size_t)(bm + lr) * Hsz;
    const size_t b_off = (size_t)(bn + lr) * Hsz;
    const int tm = (tid >> 4) << 2;
    const int tn = (tid & 15) << 2;
    float acc[4][4] = {};
    float4 av = *(const float4*)(g_h1all + a_off + lk);
    float4 bv = __ldcg((const float4*)(Wo + b_off + lk));
    for (int k0 = 0; k0 < Hsz; k0 += 16) {
        float* As = stage + (((k0 >> 4) & 1) << 11);
        float* Bs = As + 1024;
        As[(lk + 0) * 64 + lr] = av.x; As[(lk + 1) * 64 + lr] = av.y;
        As[(lk + 2) * 64 + lr] = av.z; As[(lk + 3) * 64 + lr] = av.w;
        Bs[(lk + 0) * 64 + lr] = bv.x; Bs[(lk + 1) * 64 + lr] = bv.y;
        Bs[(lk + 2) * 64 + lr] = bv.z; Bs[(lk + 3) * 64 + lr] = bv.w;
        __syncthreads();
        if (k0 + 16 < Hsz) {
            av = *(const float4*)(g_h1all + a_off + k0 + 16 + lk);
            bv = __ldcg((const float4*)(Wo + b_off + k0 + 16 + lk));
        }
#pragma unroll
        for (int kk = 0; kk < 16; kk++) {
            float4 a = *(const float4*)(As + kk * 64 + tm);
            float4 b = *(const float4*)(Bs + kk * 64 + tn);
            FMA16();
        }
    }
#pragma unroll
    for (int i = 0; i < 4; i++) {
        int m = bm + tm + i;
        int bb = m & 31;
        int s = m >> 5;
        size_t ro = ((size_t)bb * Ssz + s) * Osz;
#pragma unroll
        for (int j = 0; j < 4; j++) {
            int n = bn + tn + j;
            out[ro + n] = acc[i][j] + bo[n];
        }
    }
}

// ---------------- async chunk issue (64 k, hi+lo, A 32 rows + B 64 rows) ----------------
__device__ __forceinline__ void issue_chunk(
    const __nv_bfloat16* __restrict__ Ah, const __nv_bfloat16* __restrict__ Al,
    const __nv_bfloat16* __restrict__ Wbh, const __nv_bfloat16* __restrict__ Wbl,
    int n0, int kk, __nv_bfloat16* st, int arow, int koct)
{
    uint32_t base = smaddr(st);
    uint32_t dA = base + (uint32_t)(arow * 72 + koct) * 2;
    const size_t asrc = (size_t)arow * Hsz + kk + koct;
    cpa16(dA,        Ah + asrc);
    cpa16(dA + 4608, Al + asrc);
    const size_t b0 = (size_t)(n0 + arow) * Hsz + kk + koct;
    const size_t b1 = (size_t)(n0 + arow + 32) * Hsz + kk + koct;
    uint32_t dB = base + 9216 + (uint32_t)(arow * 72 + koct) * 2;
    cpa16(dB,               Wbh + b0);
    cpa16(dB + 4608,        Wbh + b1);
    cpa16(dB + 9216,        Wbl + b0);
    cpa16(dB + 9216 + 4608, Wbl + b1);
    asm volatile("cp.async.commit_group;" ::: "memory");
}

// ---------------- pipelined split-bf16 MMA tile, prefetch depth 3 ----------------
__device__ __forceinline__ void mma_tile_async(
    const __nv_bfloat16* __restrict__ Ah, const __nv_bfloat16* __restrict__ Al,
    const __nv_bfloat16* __restrict__ Wbh, const __nv_bfloat16* __restrict__ Wbl,
    int n0, int kbase, int nchunks, int tid, float cacc[2][4], __nv_bfloat16* sm)
{
    const int lane = tid & 31, warp = tid >> 5;
    const int m0 = (warp & 1) << 4, nw = (warp >> 1) << 4;
    const int arow = tid >> 3, koct = (tid & 7) << 3;
    const int aoff = (m0 + (lane & 15)) * 72 + ((lane >> 4) << 3);
    const int boff = (nw + (lane & 15)) * 72 + ((lane >> 4) << 3);

#pragma unroll
    for (int i = 0; i < 3; i++) {
        if (i < nchunks)
            issue_chunk(Ah, Al, Wbh, Wbl, n0, kbase + (i << 6), sm + i * STG_ELEMS, arow, koct);
        else
            asm volatile("cp.async.commit_group;" ::: "memory");
    }

    for (int kc = 0; kc < nchunks; kc++) {
        asm volatile("cp.async.wait_group 2;" ::: "memory");
        __syncthreads();
        const int nx = kc + 3;
        if (nx < nchunks)
            issue_chunk(Ah, Al, Wbh, Wbl, n0, kbase + (nx << 6),
                        sm + (nx & 3) * STG_ELEMS, arow, koct);
        else
            asm volatile("cp.async.commit_group;" ::: "memory");
        __nv_bfloat16* st = sm + (kc & 3) * STG_ELEMS;
        uint32_t adAh = smaddr(st + aoff);
        uint32_t adAl = smaddr(st + 2304 + aoff);
        uint32_t adBh = smaddr(st + 4608 + boff);
        uint32_t adBl = smaddr(st + 9216 + boff);
#pragma unroll
        for (int ks = 0; ks < 4; ks++) {
            const uint32_t ko = ks << 5;
            uint32_t ah0, ah1, ah2, ah3, al0, al1, al2, al3;
            uint32_t bh0, bh1, bh2, bh3, bl0, bl1, bl2, bl3;
            ldsm4(adAh + ko, ah0, ah1, ah2, ah3);
            ldsm4(adAl + ko, al0, al1, al2, al3);
            ldsm4(adBh + ko, bh0, bh1, bh2, bh3);
            ldsm4(adBl + ko, bl0, bl1, bl2, bl3);
            mma16816(cacc[0], ah0, ah1, ah2, ah3, bh0, bh2);
            mma16816(cacc[0], ah0, ah1, ah2, ah3, bl0, bl2);
            mma16816(cacc[0], al0, al1, al2, al3, bh0, bh2);
            mma16816(cacc[1], ah0, ah1, ah2, ah3, bh1, bh3);
            mma16816(cacc[1], ah0, ah1, ah2, ah3, bl1, bl3);
            mma16816(cacc[1], al0, al1, al2, al3, bh1, bh3);
        }
    }
}

// store fragments to a fp32 partial plane at [(m<<10) + n0 + col]
#define FRAG_STORE(dst) do { \
    _Pragma("unroll") for (int j_ = 0; j_ < 2; j_++) \
    _Pragma("unroll") for (int e_ = 0; e_ < 4; e_++) { \
        int m_ = erow + ((e_ >> 1) << 3); \
        int i_ = n0 + ecol + (j_ << 3) + (e_ & 1); \
        (dst)[(m_ << 10) + i_] = cacc[j_][e_]; \
    } } while (0)

// ---------------- persistent recurrence kernel ----------------
__global__ __launch_bounds__(256, 1) void k_recur(const float* __restrict__ bxp) {
    extern __shared__ __nv_bfloat16 smdyn[];
    __shared__ int s_win;
    const int tid = threadIdx.x;
    const int b = blockIdx.x;
    const int lane = tid & 31, warp = tid >> 5;
    const int erow = ((warp & 1) << 4) + (lane >> 2);
    const int ecol = ((warp >> 1) << 4) + ((lane & 3) << 1);
    unsigned bar = 0;

    for (int t = 0; t < Ssz; t++) {
        const float* xp = g_xp0 + (size_t)t * Bsz * 3072;

        // ---- Phase A (128 blocks): z0, r0.  2 GEMMs x 16 tiles x 4 K-slices ----
        {
            const int slice = b & 3, task = b >> 2;
            const int sel = task >> 4, tile = task & 15, n0 = tile << 6;
            float cacc[2][4] = {};
            mma_tile_async(g_h0h, g_h0l, g_whh + (size_t)sel * 1048576,
                           g_whl + (size_t)sel * 1048576, n0, slice << 8, 4,
                           tid, cacc, smdyn);
            FRAG_STORE(g_pA + (((slice << 1) + sel) << 15));
            __threadfence();
            __syncthreads();
            if (tid == 0) s_win = ((atomicAdd(&g_tkA[task], 1u) & 3u) == 3u) ? 1 : 0;
            __syncthreads();
            if (s_win) {
                const float* p = g_pA + (sel << 15);
#pragma unroll
                for (int jj = 0; jj < 8; jj++) {
                    int e = tid + (jj << 8);
                    int m = e >> 6;
                    int i = n0 + (e & 63);
                    int off = (m << 10) + i;
                    float v = __ldcg(p + off) + __ldcg(p + 65536 + off)
                            + __ldcg(p + 131072 + off) + __ldcg(p + 196608 + off);
                    if (sel == 0) g_z0[off] = sigf(v + xp[m * 3072 + i]);
                    else {
                        float r = sigf(v + xp[m * 3072 + 1024 + i]);
                        split_bf16(r * g_h0[off], &g_rh0h[off], &g_rh0l[off]);
                    }
                }
            }
        }
        gridbar(++bar);

        // ---- Phase B (128 blocks): L0 candidate; 16 tiles x 8 K-slices (2 chunks) ----
        {
            const int slice = b & 7, tile = b >> 3, n0 = tile << 6;
            float cacc[2][4] = {};
            mma_tile_async(g_rh0h, g_rh0l, g_whh + (size_t)2 * 1048576,
                           g_whl + (size_t)2 * 1048576, n0, slice << 7, 2,
                           tid, cacc, smdyn);
            FRAG_STORE(g_pB + (slice << 15));
            __threadfence();
            __syncthreads();
            if (tid == 0) s_win = ((atomicAdd(&g_tkB[tile], 1u) & 7u) == 7u) ? 1 : 0;
            __syncthreads();
            if (s_win) {
#pragma unroll
                for (int jj = 0; jj < 8; jj++) {
                    int e = tid + (jj << 8);
                    int m = e >> 6;
                    int i = n0 + (e & 63);
                    int off = (m << 10) + i;
                    float v = 0.f;
#pragma unroll
                    for (int s = 0; s < 8; s++) v += __ldcg(g_pB + (s << 15) + off);
                    float c = tanhf(v + xp[m * 3072 + 2048 + i]);
                    float z = g_z0[off];
                    float h = g_h0[off];
                    float hn = z * h + (1.f - z) * c;
                    g_h0[off] = hn;
                    split_bf16(hn, &g_h0h[off], &g_h0l[off]);
                }
            }
        }
        gridbar(++bar);

        // ---- Phase C (128 blocks): L1 z,r as virtual K=2048 over [h0;h1] ----
        // slices 0,1: h0 @ Wx[1][gate] (k=slice*512); slices 2,3: h1 @ Wh[1][gate]
        {
            const int slice = b & 3, task = b >> 2;
            const int gate = task >> 4, tile = task & 15, n0 = tile << 6;
            float cacc[2][4] = {};
            if (slice < 2)
                mma_tile_async(g_h0h, g_h0l, g_wxh + (size_t)gate * 1048576,
                               g_wxl + (size_t)gate * 1048576, n0, slice << 9, 8,
                               tid, cacc, smdyn);
            else
                mma_tile_async(g_h1h, g_h1l, g_whh + (size_t)(3 + gate) * 1048576,
                               g_whl + (size_t)(3 + gate) * 1048576, n0, (slice - 2) << 9, 8,
                               tid, cacc, smdyn);
            FRAG_STORE(g_pC + (((slice << 1) + gate) << 15));
            __threadfence();
            __syncthreads();
            if (tid == 0) s_win = ((atomicAdd(&g_tkC[task], 1u) & 3u) == 3u) ? 1 : 0;
            __syncthreads();
            if (s_win) {
                const float* p = g_pC + (gate << 15);
#pragma unroll
                for (int jj = 0; jj < 8; jj++) {
                    int e = tid + (jj << 8);
                    int m = e >> 6;
                    int i = n0 + (e & 63);
                    int off = (m << 10) + i;
                    float val = __ldcg(p + off) + __ldcg(p + 65536 + off)
                              + __ldcg(p + 131072 + off) + __ldcg(p + 196608 + off)
                              + bxp[3072 + (gate << 10) + i];
                    if (gate == 0) g_z1[off] = sigf(val);
                    else {
                        float r = sigf(val);
                        split_bf16(r * g_h1[off], &g_rh1h[off], &g_rh1l[off]);
                    }
                }
            }
        }
        gridbar(++bar);

        // ---- Phase D (128 blocks): L1 candidate as virtual K=2048 over [rh1;h0] ----
        // slices 0-3: rh1 @ Wh[1][2] (k=slice*256); slices 4-7: h0 @ Wx[1][2]
        {
            const int slice = b & 7, tile = b >> 3, n0 = tile << 6;
            float cacc[2][4] = {};
            if (slice < 4)
                mma_tile_async(g_rh1h, g_rh1l, g_whh + (size_t)5 * 1048576,
                               g_whl + (size_t)5 * 1048576, n0, slice << 8, 4,
                               tid, cacc, smdyn);
            else
                mma_tile_async(g_h0h, g_h0l, g_wxh + (size_t)2 * 1048576,
                               g_wxl + (size_t)2 * 1048576, n0, (slice - 4) << 8, 4,
                               tid, cacc, smdyn);
            FRAG_STORE(g_pD + (slice << 15));
            __threadfence();
            __syncthreads();
            if (tid == 0) s_win = ((atomicAdd(&g_tkD[tile], 1u) & 7u) == 7u) ? 1 : 0;
            __syncthreads();
            if (s_win) {
#pragma unroll
                for (int jj = 0; jj < 8; jj++) {
                    int e = tid + (jj << 8);
                    int m = e >> 6;
                    int i = n0 + (e & 63);
                    int off = (m << 10) + i;
                    float v = 0.f;
#pragma unroll
                    for (int s = 0; s < 8; s++) v += __ldcg(g_pD + (s << 15) + off);
                    float c = tanhf(v + bxp[3072 + 2048 + i]);
                    float z = g_z1[off];
                    float h = g_h1[off];
                    float hn = z * h + (1.f - z) * c;
                    g_h1[off] = hn;
                    split_bf16(hn, &g_h1h[off], &g_h1l[off]);
                    g_h1all[(size_t)t * Bsz * Hsz + off] = hn;
                }
            }
        }
        gridbar(++bar);
    }
}

// ---- final hidden state (B,L,H) appended after layer_output ----
__global__ void k_hid(float* __restrict__ out) {
    int idx = blockIdx.x * blockDim.x + threadIdx.x;
    int b = idx >> 11;
    int r = idx & 2047;
    int l = r >> 10;
    int i = r & 1023;
    out[(size_t)Bsz * Ssz * Osz + idx] = (l == 0 ? g_h0 : g_h1)[b * Hsz + i];
}

// ---------------- launch (6 graph nodes) ----------------
extern "C" void kernel_launch(void* const* d_in, const int* in_sizes, int n_in,
                              void* d_out, int out_size) {
    const float* x   = (const float*)d_in[0];
    const float* h0  = (const float*)d_in[1];
    const float* Wx  = (const float*)d_in[2];
    const float* Wh  = (const float*)d_in[3];
    const float* bx  = (const float*)d_in[4];
    const float* Wo  = (const float*)d_in[5];
    const float* bo  = (const float*)d_in[6];
    float* out = (float*)d_out;

    cudaFuncSetAttribute(k_recur, cudaFuncAttributeMaxDynamicSharedMemorySize, SMEM_BYTES);

    k_init<<<64, 1024>>>(h0);
    k_wconv<<<9216, 1024>>>(Wh, Wx);
    k_xproj<<<dim3(48, 256), 256>>>(x, Wx, bx);
    k_recur<<<GRID, 256, SMEM_BYTES>>>(bx);
    k_out<<<dim3(16, 256), 256>>>(Wo, bo, out);
    k_hid<<<64, 1024>>>(out);
}

// round 14
// speedup vs baseline: 1.8868x; 1.4839x over previous
#include <cuda_runtime.h>
#include <cuda_bf16.h>
#include <stdint.h>
#include <stddef.h>
#include <math.h>

#define Bsz 32
#define Ssz 512
#define Hsz 1024
#define Osz 1024
#define GRID 128

// stage layout (bf16 elems): A_h[32*72] | A_l[32*72] | B_h[64*72] | B_l[64*72]
#define STG_ELEMS 13824          // 192*72
#define SMEM_BYTES (4 * STG_ELEMS * 2)   // 110592

// ---------------- device scratch ----------------
__device__ float g_xp0[(size_t)Ssz * Bsz * 3 * Hsz];
__device__ float g_h1all[(size_t)Ssz * Bsz * Hsz];
__device__ float g_h0[Bsz * Hsz];
__device__ float g_h1[Bsz * Hsz];
__device__ float g_z0[Bsz * Hsz];
__device__ float g_z1[Bsz * Hsz];
__device__ float g_gc1[Bsz * Hsz];
// split-bf16 activations
__device__ __align__(16) __nv_bfloat16 g_h0h[Bsz * Hsz], g_h0l[Bsz * Hsz];
__device__ __align__(16) __nv_bfloat16 g_h1h[Bsz * Hsz], g_h1l[Bsz * Hsz];
__device__ __align__(16) __nv_bfloat16 g_rh0h[Bsz * Hsz], g_rh0l[Bsz * Hsz];
__device__ __align__(16) __nv_bfloat16 g_rh1h[Bsz * Hsz], g_rh1l[Bsz * Hsz];
// split-bf16 weights
__device__ __align__(16) __nv_bfloat16 g_whh[6 * 1048576], g_whl[6 * 1048576];
__device__ __align__(16) __nv_bfloat16 g_wxh[3 * 1048576], g_wxl[3 * 1048576];
// partial planes + tickets
__device__ float g_pA[4 * 32768];   // phase1 pair planes: z1x,z1h,r1x,r1h
__device__ float g_pB[8 * 32768];   // phase2: [unit2][slice4]
__device__ unsigned g_tk1[32], g_tk2[32];
__device__ unsigned g_barcnt;

__device__ __forceinline__ float sigf(float x) { return 1.f / (1.f + expf(-x)); }

__device__ __forceinline__ void split_bf16(float x, __nv_bfloat16* ph, __nv_bfloat16* pl) {
    __nv_bfloat16 h = __float2bfloat16(x);
    *ph = h;
    *pl = __float2bfloat16(x - __bfloat162float(h));
}

#define FMA16() do { \
    acc[0][0] += a.x*b.x; acc[0][1] += a.x*b.y; acc[0][2] += a.x*b.z; acc[0][3] += a.x*b.w; \
    acc[1][0] += a.y*b.x; acc[1][1] += a.y*b.y; acc[1][2] += a.y*b.z; acc[1][3] += a.y*b.w; \
    acc[2][0] += a.z*b.x; acc[2][1] += a.z*b.y; acc[2][2] += a.z*b.z; acc[2][3] += a.z*b.w; \
    acc[3][0] += a.w*b.x; acc[3][1] += a.w*b.y; acc[3][2] += a.w*b.z; acc[3][3] += a.w*b.w; \
} while (0)

// ---------------- grid barrier ----------------
__device__ __forceinline__ void gridbar(unsigned gen) {
    __syncthreads();
    __threadfence();
    if (threadIdx.x == 0) {
        atomicAdd(&g_barcnt, 1u);
        const unsigned tgt = gen * GRID;
        while (*(volatile unsigned*)&g_barcnt < tgt) { }
    }
    __syncthreads();
    __threadfence();
}

// ---------------- MMA / async primitives ----------------
__device__ __forceinline__ uint32_t smaddr(const void* p) {
    return (uint32_t)__cvta_generic_to_shared(p);
}
__device__ __forceinline__ void cpa16(uint32_t dst, const void* src) {
    asm volatile("cp.async.cg.shared.global [%0], [%1], 16;" :: "r"(dst), "l"(src));
}
__device__ __forceinline__ void ldsm4(uint32_t addr, uint32_t& r0, uint32_t& r1,
                                      uint32_t& r2, uint32_t& r3) {
    asm volatile("ldmatrix.sync.aligned.m8n8.x4.shared.b16 {%0,%1,%2,%3}, [%4];"
                 : "=r"(r0), "=r"(r1), "=r"(r2), "=r"(r3) : "r"(addr));
}
__device__ __forceinline__ void mma16816(float* c, uint32_t a0, uint32_t a1, uint32_t a2,
                                         uint32_t a3, uint32_t b0, uint32_t b1) {
    asm volatile("mma.sync.aligned.m16n8k16.row.col.f32.bf16.bf16.f32 "
                 "{%0,%1,%2,%3}, {%4,%5,%6,%7}, {%8,%9}, {%0,%1,%2,%3};"
                 : "+f"(c[0]), "+f"(c[1]), "+f"(c[2]), "+f"(c[3])
                 : "r"(a0), "r"(a1), "r"(a2), "r"(a3), "r"(b0), "r"(b1));
}

// ---------------- init ----------------
__global__ void k_init(const float* __restrict__ h0in) {
    if (blockIdx.x == 0 && threadIdx.x == 0) g_barcnt = 0u;
    int idx = blockIdx.x * blockDim.x + threadIdx.x;
    int b = idx >> 11;
    int r = idx & 2047;
    int l = r >> 10;
    int i = r & 1023;
    float v = h0in[idx];
    int off = b * Hsz + i;
    if (l == 0) { g_h0[off] = v; split_bf16(v, &g_h0h[off], &g_h0l[off]); }
    else        { g_h1[off] = v; split_bf16(v, &g_h1h[off], &g_h1l[off]); }
}

// ---------------- weight conversion ----------------
__global__ void k_wconv(const float* __restrict__ Wh, const float* __restrict__ Wx) {
    size_t idx = (size_t)blockIdx.x * 1024 + threadIdx.x;
    if (idx < 6291456) {
        float v = Wh[idx];
        split_bf16(v, &g_whh[idx], &g_whl[idx]);
    } else {
        size_t o = idx - 6291456;
        float v = Wx[3145728 + o];
        split_bf16(v, &g_wxh[o], &g_wxl[o]);
    }
}

// ---------------- big GEMM: xp0 = x @ Wx[0]^T + bx[0] (fp32) ----------------
__global__ __launch_bounds__(256) void k_xproj(const float* __restrict__ x,
                                               const float* __restrict__ Wx,
                                               const float* __restrict__ bxp) {
    __shared__ __align__(16) float stage[4096];
    const int tid = threadIdx.x;
    const int bm = blockIdx.y << 6;
    const int bn = blockIdx.x << 6;
    const int lr = tid >> 2;
    const int lk = (tid & 3) << 2;
    const int mrow = bm + lr;
    const size_t a_off = ((size_t)(mrow & 31) * Ssz + (mrow >> 5)) * Hsz;
    const size_t b_off = (size_t)(bn + lr) * Hsz;
    const int tm = (tid >> 4) << 2;
    const int tn = (tid & 15) << 2;
    float acc[4][4] = {};
    float4 av = *(const float4*)(x + a_off + lk);
    float4 bv = __ldcg((const float4*)(Wx + b_off + lk));
    for (int k0 = 0; k0 < Hsz; k0 += 16) {
        float* As = stage + (((k0 >> 4) & 1) << 11);
        float* Bs = As + 1024;
        As[(lk + 0) * 64 + lr] = av.x; As[(lk + 1) * 64 + lr] = av.y;
        As[(lk + 2) * 64 + lr] = av.z; As[(lk + 3) * 64 + lr] = av.w;
        Bs[(lk + 0) * 64 + lr] = bv.x; Bs[(lk + 1) * 64 + lr] = bv.y;
        Bs[(lk + 2) * 64 + lr] = bv.z; Bs[(lk + 3) * 64 + lr] = bv.w;
        __syncthreads();
        if (k0 + 16 < Hsz) {
            av = *(const float4*)(x + a_off + k0 + 16 + lk);
            bv = __ldcg((const float4*)(Wx + b_off + k0 + 16 + lk));
        }
#pragma unroll
        for (int kk = 0; kk < 16; kk++) {
            float4 a = *(const float4*)(As + kk * 64 + tm);
            float4 b = *(const float4*)(Bs + kk * 64 + tn);
            FMA16();
        }
    }
#pragma unroll
    for (int i = 0; i < 4; i++) {
        size_t ro = (size_t)(bm + tm + i) * 3072;
#pragma unroll
        for (int j = 0; j < 4; j++) {
            int n = bn + tn + j;
            g_xp0[ro + n] = acc[i][j] + bxp[n];
        }
    }
}

// ---------------- big GEMM: out = h1all @ Wo^T + bo (fp32) ----------------
__global__ __launch_bounds__(256) void k_out(const float* __restrict__ Wo,
                                             const float* __restrict__ bo,
                                             float* __restrict__ out) {
    __shared__ __align__(16) float stage[4096];
    const int tid = threadIdx.x;
    const int bm = blockIdx.y << 6;
    const int bn = blockIdx.x << 6;
    const int lr = tid >> 2;
    const int lk = (tid & 3) << 2;
    const size_t a_off = (size_t)(bm + lr) * Hsz;
    const size_t b_off = (size_t)(bn + lr) * Hsz;
    const int tm = (tid >> 4) << 2;
    const int tn = (tid & 15) << 2;
    float acc[4][4] = {};
    float4 av = *(const float4*)(g_h1all + a_off + lk);
    float4 bv = __ldcg((const float4*)(Wo + b_off + lk));
    for (int k0 = 0; k0 < Hsz; k0 += 16) {
        float* As = stage + (((k0 >> 4) & 1) << 11);
        float* Bs = As + 1024;
        As[(lk + 0) * 64 + lr] = av.x; As[(lk + 1) * 64 + lr] = av.y;
        As[(lk + 2) * 64 + lr] = av.z; As[(lk + 3) * 64 + lr] = av.w;
        Bs[(lk + 0) * 64 + lr] = bv.x; Bs[(lk + 1) * 64 + lr] = bv.y;
        Bs[(lk + 2) * 64 + lr] = bv.z; Bs[(lk + 3) * 64 + lr] = bv.w;
        __syncthreads();
        if (k0 + 16 < Hsz) {
            av = *(const float4*)(g_h1all + a_off + k0 + 16 + lk);
            bv = __ldcg((const float4*)(Wo + b_off + k0 + 16 + lk));
        }
#pragma unroll
        for (int kk = 0; kk < 16; kk++) {
            float4 a = *(const float4*)(As + kk * 64 + tm);
            float4 b = *(const float4*)(Bs + kk * 64 + tn);
            FMA16();
        }
    }
#pragma unroll
    for (int i = 0; i < 4; i++) {
        int m = bm + tm + i;
        int bb = m & 31;
        int s = m >> 5;
        size_t ro = ((size_t)bb * Ssz + s) * Osz;
#pragma unroll
        for (int j = 0; j < 4; j++) {
            int n = bn + tn + j;
            out[ro + n] = acc[i][j] + bo[n];
        }
    }
}

// ---------------- async chunk issue (64 k, hi+lo, A 32 rows + B 64 rows) ----------------
__device__ __forceinline__ void issue_chunk(
    const __nv_bfloat16* __restrict__ Ah, const __nv_bfloat16* __restrict__ Al,
    const __nv_bfloat16* __restrict__ Wbh, const __nv_bfloat16* __restrict__ Wbl,
    int n0, int kk, __nv_bfloat16* st, int arow, int koct)
{
    uint32_t base = smaddr(st);
    uint32_t dA = base + (uint32_t)(arow * 72 + koct) * 2;
    const size_t asrc = (size_t)arow * Hsz + kk + koct;
    cpa16(dA,        Ah + asrc);
    cpa16(dA + 4608, Al + asrc);
    const size_t b0 = (size_t)(n0 + arow) * Hsz + kk + koct;
    const size_t b1 = (size_t)(n0 + arow + 32) * Hsz + kk + koct;
    uint32_t dB = base + 9216 + (uint32_t)(arow * 72 + koct) * 2;
    cpa16(dB,               Wbh + b0);
    cpa16(dB + 4608,        Wbh + b1);
    cpa16(dB + 9216,        Wbl + b0);
    cpa16(dB + 9216 + 4608, Wbl + b1);
    asm volatile("cp.async.commit_group;" ::: "memory");
}

// ---------------- pipelined split-bf16 MMA tile, prefetch depth 3 ----------------
__device__ __forceinline__ void mma_tile_async(
    const __nv_bfloat16* __restrict__ Ah, const __nv_bfloat16* __restrict__ Al,
    const __nv_bfloat16* __restrict__ Wbh, const __nv_bfloat16* __restrict__ Wbl,
    int n0, int kbase, int nchunks, int tid, float cacc[2][4], __nv_bfloat16* sm)
{
    const int lane = tid & 31, warp = tid >> 5;
    const int m0 = (warp & 1) << 4, nw = (warp >> 1) << 4;
    const int arow = tid >> 3, koct = (tid & 7) << 3;
    const int aoff = (m0 + (lane & 15)) * 72 + ((lane >> 4) << 3);
    const int boff = (nw + (lane & 15)) * 72 + ((lane >> 4) << 3);

#pragma unroll
    for (int i = 0; i < 3; i++) {
        if (i < nchunks)
            issue_chunk(Ah, Al, Wbh, Wbl, n0, kbase + (i << 6), sm + i * STG_ELEMS, arow, koct);
        else
            asm volatile("cp.async.commit_group;" ::: "memory");
    }

    for (int kc = 0; kc < nchunks; kc++) {
        asm volatile("cp.async.wait_group 2;" ::: "memory");
        __syncthreads();
        const int nx = kc + 3;
        if (nx < nchunks)
            issue_chunk(Ah, Al, Wbh, Wbl, n0, kbase + (nx << 6),
                        sm + (nx & 3) * STG_ELEMS, arow, koct);
        else
            asm volatile("cp.async.commit_group;" ::: "memory");
        __nv_bfloat16* st = sm + (kc & 3) * STG_ELEMS;
        uint32_t adAh = smaddr(st + aoff);
        uint32_t adAl = smaddr(st + 2304 + aoff);
        uint32_t adBh = smaddr(st + 4608 + boff);
        uint32_t adBl = smaddr(st + 9216 + boff);
#pragma unroll
        for (int ks = 0; ks < 4; ks++) {
            const uint32_t ko = ks << 5;
            uint32_t ah0, ah1, ah2, ah3, al0, al1, al2, al3;
            uint32_t bh0, bh1, bh2, bh3, bl0, bl1, bl2, bl3;
            ldsm4(adAh + ko, ah0, ah1, ah2, ah3);
            ldsm4(adAl + ko, al0, al1, al2, al3);
            ldsm4(adBh + ko, bh0, bh1, bh2, bh3);
            ldsm4(adBl + ko, bl0, bl1, bl2, bl3);
            mma16816(cacc[0], ah0, ah1, ah2, ah3, bh0, bh2);
            mma16816(cacc[0], ah0, ah1, ah2, ah3, bl0, bl2);
            mma16816(cacc[0], al0, al1, al2, al3, bh0, bh2);
            mma16816(cacc[1], ah0, ah1, ah2, ah3, bh1, bh3);
            mma16816(cacc[1], ah0, ah1, ah2, ah3, bl1, bl3);
            mma16816(cacc[1], al0, al1, al2, al3, bh1, bh3);
        }
    }
}

// store fragments to a fp32 partial plane at [(m<<10) + n0 + col]
#define FRAG_STORE(dst) do { \
    _Pragma("unroll") for (int j_ = 0; j_ < 2; j_++) \
    _Pragma("unroll") for (int e_ = 0; e_ < 4; e_++) { \
        int m_ = erow + ((e_ >> 1) << 3); \
        int i_ = n0 + ecol + (j_ << 3) + (e_ & 1); \
        (dst)[(m_ << 10) + i_] = cacc[j_][e_]; \
    } } while (0)

// iterate over a block's 8 fragment elements: provides m_, i_, off_, val_
#define FRAG_FOREACH(BODY) do { \
    _Pragma("unroll") for (int j_ = 0; j_ < 2; j_++) \
    _Pragma("unroll") for (int e_ = 0; e_ < 4; e_++) { \
        int m_ = erow + ((e_ >> 1) << 3); \
        int i_ = n0 + ecol + (j_ << 3) + (e_ & 1); \
        int off_ = (m_ << 10) + i_; \
        float val_ = cacc[j_][e_]; \
        BODY \
    } } while (0)

// ---------------- persistent recurrence kernel (2 phases / step) ----------------
__global__ __launch_bounds__(256, 1) void k_recur(const float* __restrict__ bxp) {
    extern __shared__ __nv_bfloat16 smdyn[];
    __shared__ int s_win;
    const int tid = threadIdx.x;
    const int b = blockIdx.x;
    const int lane = tid & 31, warp = tid >> 5;
    const int erow = ((warp & 1) << 4) + (lane >> 2);
    const int ecol = ((warp >> 1) << 4) + ((lane & 3) << 1);
    unsigned bar = 0;

    for (int u = 0; u <= Ssz; u++) {
        const float* xp = g_xp0 + (size_t)u * Bsz * 3072;   // valid only when u < Ssz

        // ======== Phase 1 (112 blocks): 7 unit-GEMMs, full K=1024 ========
        // u0: z0raw=h0@Wh[0][0]   u1: r0raw=h0@Wh[0][1]       (t = u)
        // u2: z1x=h0@Wx[1][0]     u3: z1h=h1@Wh[1][0]          (t = u-1)
        // u4: r1x=h0@Wx[1][1]     u5: r1h=h1@Wh[1][1]
        // u6: gc1=h0@Wx[1][2]
        if (b < 112) {
            const int unit = b >> 4, tile = b & 15, n0 = tile << 6;
            const bool useh1 = (unit == 3 || unit == 5);
            const __nv_bfloat16* Ah_ = useh1 ? g_h1h : g_h0h;
            const __nv_bfloat16* Al_ = useh1 ? g_h1l : g_h0l;
            const __nv_bfloat16 *Wh_, *Wl_;
            if (unit < 2)        { Wh_ = g_whh + (size_t)unit * 1048576; Wl_ = g_whl + (size_t)unit * 1048576; }
            else if (unit == 3)  { Wh_ = g_whh + (size_t)3 * 1048576;    Wl_ = g_whl + (size_t)3 * 1048576; }
            else if (unit == 5)  { Wh_ = g_whh + (size_t)4 * 1048576;    Wl_ = g_whl + (size_t)4 * 1048576; }
            else {
                int gate = (unit == 2) ? 0 : (unit == 4) ? 1 : 2;
                Wh_ = g_wxh + (size_t)gate * 1048576;
                Wl_ = g_wxl + (size_t)gate * 1048576;
            }
            float cacc[2][4] = {};
            mma_tile_async(Ah_, Al_, Wh_, Wl_, n0, 0, 16, tid, cacc, smdyn);

            if (unit == 0) {
                if (u < Ssz)
                    FRAG_FOREACH( g_z0[off_] = sigf(val_ + xp[m_ * 3072 + i_]); );
            } else if (unit == 1) {
                if (u < Ssz)
                    FRAG_FOREACH(
                        float r = sigf(val_ + xp[m_ * 3072 + 1024 + i_]);
                        split_bf16(r * g_h0[off_], &g_rh0h[off_], &g_rh0l[off_]);
                    );
            } else if (unit == 6) {
                FRAG_FOREACH( g_gc1[off_] = val_ + bxp[3072 + 2048 + i_]; );
            } else {
                const int plane = unit - 2;           // 0:z1x 1:z1h 2:r1x 3:r1h
                const int gate = plane >> 1;          // 0:z1  1:r1
                FRAG_STORE(g_pA + ((size_t)plane << 15));
                __threadfence();
                __syncthreads();
                if (tid == 0) s_win = ((atomicAdd(&g_tk1[(gate << 4) + tile], 1u) & 1u) == 1u) ? 1 : 0;
                __syncthreads();
                if (s_win) {
                    const float* px = g_pA + ((size_t)(gate << 1) << 15);
                    const float* ph = g_pA + ((size_t)((gate << 1) + 1) << 15);
#pragma unroll
                    for (int jj = 0; jj < 8; jj++) {
                        int e = tid + (jj << 8);
                        int m = e >> 6;
                        int i = n0 + (e & 63);
                        int off = (m << 10) + i;
                        float val = __ldcg(px + off) + __ldcg(ph + off)
                                  + bxp[3072 + (gate << 10) + i];
                        if (gate == 0) g_z1[off] = sigf(val);
                        else {
                            float r = sigf(val);
                            split_bf16(r * g_h1[off], &g_rh1h[off], &g_rh1l[off]);
                        }
                    }
                }
            }
        }
        gridbar(++bar);

        // ======== Phase 2 (128 blocks): cand0 (t=u) + cand1 (t=u-1), K-split x4 ========
        {
            const int unit = b >> 6, tile = (b >> 2) & 15, slice = b & 3, n0 = tile << 6;
            float cacc[2][4] = {};
            if (unit == 0)
                mma_tile_async(g_rh0h, g_rh0l, g_whh + (size_t)2 * 1048576,
                               g_whl + (size_t)2 * 1048576, n0, slice << 8, 4,
                               tid, cacc, smdyn);
            else
                mma_tile_async(g_rh1h, g_rh1l, g_whh + (size_t)5 * 1048576,
                               g_whl + (size_t)5 * 1048576, n0, slice << 8, 4,
                               tid, cacc, smdyn);
            FRAG_STORE(g_pB + ((size_t)((unit << 2) + slice) << 15));
            __threadfence();
            __syncthreads();
            if (tid == 0) s_win = ((atomicAdd(&g_tk2[(unit << 4) + tile], 1u) & 3u) == 3u) ? 1 : 0;
            __syncthreads();
            if (s_win) {
                if (unit == 0) {
                    if (u < Ssz) {
#pragma unroll
                        for (int jj = 0; jj < 8; jj++) {
                            int e = tid + (jj << 8);
                            int m = e >> 6;
                            int i = n0 + (e & 63);
                            int off = (m << 10) + i;
                            float v = __ldcg(g_pB + off) + __ldcg(g_pB + 32768 + off)
                                    + __ldcg(g_pB + 65536 + off) + __ldcg(g_pB + 98304 + off);
                            float c = tanhf(v + xp[m * 3072 + 2048 + i]);
                            float z = g_z0[off];
                            float h = g_h0[off];
                            float hn = z * h + (1.f - z) * c;
                            g_h0[off] = hn;
                            split_bf16(hn, &g_h0h[off], &g_h0l[off]);
                        }
                    }
                } else {
                    if (u >= 1) {
                        const float* pd = g_pB + 131072;
#pragma unroll
                        for (int jj = 0; jj < 8; jj++) {
                            int e = tid + (jj << 8);
                            int m = e >> 6;
                            int i = n0 + (e & 63);
                            int off = (m << 10) + i;
                            float v = __ldcg(pd + off) + __ldcg(pd + 32768 + off)
                                    + __ldcg(pd + 65536 + off) + __ldcg(pd + 98304 + off);
                            float c = tanhf(v + g_gc1[off]);
                            float z = g_z1[off];
                            float h = g_h1[off];
                            float hn = z * h + (1.f - z) * c;
                            g_h1[off] = hn;
                            split_bf16(hn, &g_h1h[off], &g_h1l[off]);
                            g_h1all[(size_t)(u - 1) * Bsz * Hsz + off] = hn;
                        }
                    }
                }
            }
        }
        gridbar(++bar);
    }
}

// ---- final hidden state (B,L,H) appended after layer_output ----
__global__ void k_hid(float* __restrict__ out) {
    int idx = blockIdx.x * blockDim.x + threadIdx.x;
    int b = idx >> 11;
    int r = idx & 2047;
    int l = r >> 10;
    int i = r & 1023;
    out[(size_t)Bsz * Ssz * Osz + idx] = (l == 0 ? g_h0 : g_h1)[b * Hsz + i];
}

// ---------------- launch (6 graph nodes) ----------------
extern "C" void kernel_launch(void* const* d_in, const int* in_sizes, int n_in,
                              void* d_out, int out_size) {
    const float* x   = (const float*)d_in[0];
    const float* h0  = (const float*)d_in[1];
    const float* Wx  = (const float*)d_in[2];
    const float* Wh  = (const float*)d_in[3];
    const float* bx  = (const float*)d_in[4];
    const float* Wo  = (const float*)d_in[5];
    const float* bo  = (const float*)d_in[6];
    float* out = (float*)d_out;

    cudaFuncSetAttribute(k_recur, cudaFuncAttributeMaxDynamicSharedMemorySize, SMEM_BYTES);

    k_init<<<64, 1024>>>(h0);
    k_wconv<<<9216, 1024>>>(Wh, Wx);
    k_xproj<<<dim3(48, 256), 256>>>(x, Wx, bx);
    k_recur<<<GRID, 256, SMEM_BYTES>>>(bx);
    k_out<<<dim3(16, 256), 256>>>(Wo, bo, out);
    k_hid<<<64, 1024>>>(out);
}